// round 5
// baseline (speedup 1.0000x reference)
#include <cuda_runtime.h>
#include <cstdint>

// EdgeModel: out[e,:] = relu([src,dest,attr,u[batch]] @ W1 + b1) @ W2 + b2
// E = 8e6, B = 4096, W1:(4,10), W2:(10,19). Output [E,19] f32.
//
//  - batch dtype (int32 vs int64) detected at runtime by a tiny kernel
//    (JAX silently downcasts int64->int32 when x64 is disabled).
//  - 2 edges per thread, packed f32x2 math (fma.rn.f32x2).
//  - Weights staged in smem as duplicated {w,w} pairs; W2 transposed for
//    contiguous 128-bit smem reads.
//  - Output staged in a 512x19 smem tile, stored as coalesced float4.

#define TPB 256
#define EDGES_PER_BLOCK 512   // TPB * 2

typedef unsigned long long u64;

__device__ int g_batch_is64;   // 1 if batch is int64, 0 if int32

__device__ __forceinline__ u64 pack2(float lo, float hi) {
    u64 r;
    asm("mov.b64 %0, {%1, %2};" : "=l"(r) : "f"(lo), "f"(hi));
    return r;
}

__device__ __forceinline__ void unpack2(u64 v, float& lo, float& hi) {
    asm("mov.b64 {%0, %1}, %2;" : "=f"(lo), "=f"(hi) : "l"(v));
}

__device__ __forceinline__ u64 fma2(u64 a, u64 b, u64 c) {
    u64 d;
    asm("fma.rn.f32x2 %0, %1, %2, %3;" : "=l"(d) : "l"(a), "l"(b), "l"(c));
    return d;
}

__device__ __forceinline__ u64 relu2(u64 v) {
    float lo, hi;
    unpack2(v, lo, hi);
    lo = fmaxf(lo, 0.0f);
    hi = fmaxf(hi, 0.0f);
    return pack2(lo, hi);
}

// Detect batch dtype: if int64 with small values, every odd int32 word
// (the high half) is 0. If int32, 1024 random values in [0,4096) being
// all-zero is impossible in practice.
__global__ void detect_batch_dtype(const int* __restrict__ b32) {
    if (threadIdx.x == 0) {
        int all_zero = 1;
        for (int i = 1; i < 2048; i += 2) {
            if (b32[i] != 0) { all_zero = 0; break; }
        }
        g_batch_is64 = all_zero;
    }
}

__global__ __launch_bounds__(TPB)
void edge_model_kernel(const float* __restrict__ src,
                       const float* __restrict__ dest,
                       const float* __restrict__ ea,
                       const float* __restrict__ u,
                       const void*  __restrict__ batch_raw,
                       const float* __restrict__ W1,   // [4,10]
                       const float* __restrict__ b1,   // [10]
                       const float* __restrict__ W2,   // [10,19]
                       const float* __restrict__ b2,   // [19]
                       float* __restrict__ out,        // [E,19]
                       long long E)
{
    __shared__ u64 w1p[40];                 // w1p[c*10+k] = {W1[c][k]}x2
    __shared__ u64 b1p[10];
    __shared__ __align__(16) u64 w2p[190];  // w2p[j*10+k] = {W2[k][j]}x2 (transposed)
    __shared__ u64 b2p[19];
    __shared__ __align__(16) float otile[EDGES_PER_BLOCK * 19];  // 38912 B

    const int t = threadIdx.x;
    const int is64 = g_batch_is64;

    // ---- stage weights (once per block) ----
    if (t < 40)              w1p[t]      = pack2(W1[t], W1[t]);
    else if (t < 50)         b1p[t - 40] = pack2(b1[t - 40], b1[t - 40]);
    else if (t < 69)         b2p[t - 50] = pack2(b2[t - 50], b2[t - 50]);
    if (t < 190) {
        int j = t / 10, k = t % 10;   // transpose
        float w = W2[k * 19 + j];
        w2p[t] = pack2(w, w);
    }
    __syncthreads();

    const long long base = (long long)blockIdx.x * EDGES_PER_BLOCK;

    if (base + EDGES_PER_BLOCK <= E) {
        // ================= fast path: full 512-edge block =================
        const long long p = (base >> 1) + t;   // pair index

        const float2 s = ((const float2*)src)[p];
        const float2 d = ((const float2*)dest)[p];
        const float2 a = ((const float2*)ea)[p];

        long long i0, i1;
        if (is64) {
            longlong2 bi = ((const longlong2*)batch_raw)[p];
            i0 = bi.x; i1 = bi.y;
        } else {
            int2 bi = ((const int2*)batch_raw)[p];
            i0 = bi.x; i1 = bi.y;
        }
        const float u0 = __ldg(&u[i0]);
        const float u1 = __ldg(&u[i1]);

        const u64 sp = pack2(s.x, s.y);
        const u64 dp = pack2(d.x, d.y);
        const u64 ap = pack2(a.x, a.y);
        const u64 up = pack2(u0, u1);

        // layer 1
        u64 h[10];
        #pragma unroll
        for (int k = 0; k < 10; k++) {
            u64 acc = b1p[k];
            acc = fma2(sp, w1p[k],      acc);
            acc = fma2(dp, w1p[10 + k], acc);
            acc = fma2(ap, w1p[20 + k], acc);
            acc = fma2(up, w1p[30 + k], acc);
            h[k] = relu2(acc);
        }

        // layer 2 into smem output tile
        float* row0 = &otile[(2 * t)     * 19];
        float* row1 = &otile[(2 * t + 1) * 19];
        #pragma unroll
        for (int j = 0; j < 19; j++) {
            u64 acc = b2p[j];
            const ulonglong2* wr = (const ulonglong2*)&w2p[j * 10];  // 16B aligned
            #pragma unroll
            for (int kk = 0; kk < 5; kk++) {
                ulonglong2 w = wr[kk];
                acc = fma2(h[2 * kk],     w.x, acc);
                acc = fma2(h[2 * kk + 1], w.y, acc);
            }
            float lo, hi;
            unpack2(acc, lo, hi);
            row0[j] = lo;
            row1[j] = hi;
        }
        __syncthreads();

        // coalesced cooperative store: 512*19 floats = 2432 float4
        const float4* ot4 = (const float4*)otile;
        float4* o4 = (float4*)(out + base * 19);   // base*19 % 4 == 0
        #pragma unroll
        for (int i = 0; i < 2432 / TPB; i++)
            o4[i * TPB + t] = ot4[i * TPB + t];
        {   // remainder: 2432 = 9*256 + 128
            int i = (2432 / TPB) * TPB + t;
            if (i < 2432) o4[i] = ot4[i];
        }
    } else {
        // ================= tail path (scalar, bounds-checked) =================
        for (long long e = base + t; e < E; e += TPB) {
            float x0 = src[e], x1 = dest[e], x2 = ea[e];
            long long bi = is64 ? ((const long long*)batch_raw)[e]
                                : (long long)((const int*)batch_raw)[e];
            float x3 = u[bi];
            float h[10];
            #pragma unroll
            for (int k = 0; k < 10; k++) {
                float acc = b1[k];
                acc = fmaf(x0, W1[k],      acc);
                acc = fmaf(x1, W1[10 + k], acc);
                acc = fmaf(x2, W1[20 + k], acc);
                acc = fmaf(x3, W1[30 + k], acc);
                h[k] = fmaxf(acc, 0.0f);
            }
            #pragma unroll
            for (int j = 0; j < 19; j++) {
                float acc = b2[j];
                #pragma unroll
                for (int k = 0; k < 10; k++)
                    acc = fmaf(h[k], W2[k * 19 + j], acc);
                out[e * 19 + j] = acc;
            }
        }
    }
}

extern "C" void kernel_launch(void* const* d_in, const int* in_sizes, int n_in,
                              void* d_out, int out_size)
{
    const float* src   = (const float*)d_in[0];
    const float* dest  = (const float*)d_in[1];
    const float* ea    = (const float*)d_in[2];
    const float* u     = (const float*)d_in[3];
    const void*  batch = d_in[4];
    const float* W1    = (const float*)d_in[5];
    const float* b1    = (const float*)d_in[6];
    const float* W2    = (const float*)d_in[7];
    const float* b2    = (const float*)d_in[8];
    float* out = (float*)d_out;

    const long long E = in_sizes[0];
    const int blocks = (int)((E + EDGES_PER_BLOCK - 1) / EDGES_PER_BLOCK);

    detect_batch_dtype<<<1, 32>>>((const int*)batch);
    edge_model_kernel<<<blocks, TPB>>>(src, dest, ea, u, batch,
                                       W1, b1, W2, b2, out, E);
}

// round 6
// speedup vs baseline: 1.4708x; 1.4708x over previous
#include <cuda_runtime.h>
#include <cstdint>

// EdgeModel: out[e,:] = relu([src,dest,attr,u[batch]] @ W1 + b1) @ W2 + b2
// E = 8e6, B = 4096, W1:(4,10), W2:(10,19). Output [E,19] f32.
//
// R5 changes vs R4 (which ran at 255 regs -> 1 CTA/SM -> 12% occ, latency-bound):
//  - __launch_bounds__(256, 3): cap ~85 regs -> 3 CTAs/SM (24 warps).
//  - layer-2 loop partial unroll (2) so the 95 LDS.128 weight loads are not
//    all hoisted into live registers.
// Everything else unchanged: packed f32x2 math (2 edges/thread), duplicated
// {w,w} weight pairs in smem, W2 transposed for LDS.128, 512x19 smem output
// tile flushed with coalesced float4 stores.

#define TPB 256
#define EDGES_PER_BLOCK 512   // TPB * 2

typedef unsigned long long u64;

__device__ int g_batch_is64;   // 1 if batch is int64, 0 if int32

__device__ __forceinline__ u64 pack2(float lo, float hi) {
    u64 r;
    asm("mov.b64 %0, {%1, %2};" : "=l"(r) : "f"(lo), "f"(hi));
    return r;
}

__device__ __forceinline__ void unpack2(u64 v, float& lo, float& hi) {
    asm("mov.b64 {%0, %1}, %2;" : "=f"(lo), "=f"(hi) : "l"(v));
}

__device__ __forceinline__ u64 fma2(u64 a, u64 b, u64 c) {
    u64 d;
    asm("fma.rn.f32x2 %0, %1, %2, %3;" : "=l"(d) : "l"(a), "l"(b), "l"(c));
    return d;
}

__device__ __forceinline__ u64 relu2(u64 v) {
    float lo, hi;
    unpack2(v, lo, hi);
    lo = fmaxf(lo, 0.0f);
    hi = fmaxf(hi, 0.0f);
    return pack2(lo, hi);
}

// Detect batch dtype: if int64 with small values (0..4095), every odd int32
// word (high half) is 0. 1024 random int32 in [0,4096) all zero: impossible.
__global__ void detect_batch_dtype(const int* __restrict__ b32) {
    if (threadIdx.x == 0) {
        int all_zero = 1;
        for (int i = 1; i < 2048; i += 2) {
            if (b32[i] != 0) { all_zero = 0; break; }
        }
        g_batch_is64 = all_zero;
    }
}

__global__ __launch_bounds__(TPB, 3)
void edge_model_kernel(const float* __restrict__ src,
                       const float* __restrict__ dest,
                       const float* __restrict__ ea,
                       const float* __restrict__ u,
                       const void*  __restrict__ batch_raw,
                       const float* __restrict__ W1,   // [4,10]
                       const float* __restrict__ b1,   // [10]
                       const float* __restrict__ W2,   // [10,19]
                       const float* __restrict__ b2,   // [19]
                       float* __restrict__ out,        // [E,19]
                       long long E)
{
    __shared__ u64 w1p[40];                 // w1p[c*10+k] = {W1[c][k]}x2
    __shared__ u64 b1p[10];
    __shared__ __align__(16) u64 w2p[190];  // w2p[j*10+k] = {W2[k][j]}x2 (transposed)
    __shared__ u64 b2p[19];
    __shared__ __align__(16) float otile[EDGES_PER_BLOCK * 19];  // 38912 B

    const int t = threadIdx.x;
    const int is64 = g_batch_is64;

    // ---- stage weights (once per block) ----
    if (t < 40)              w1p[t]      = pack2(W1[t], W1[t]);
    else if (t < 50)         b1p[t - 40] = pack2(b1[t - 40], b1[t - 40]);
    else if (t < 69)         b2p[t - 50] = pack2(b2[t - 50], b2[t - 50]);
    if (t < 190) {
        int j = t / 10, k = t % 10;   // transpose
        float w = W2[k * 19 + j];
        w2p[t] = pack2(w, w);
    }
    __syncthreads();

    const long long base = (long long)blockIdx.x * EDGES_PER_BLOCK;

    if (base + EDGES_PER_BLOCK <= E) {
        // ================= fast path: full 512-edge block =================
        const long long p = (base >> 1) + t;   // pair index

        const float2 s = ((const float2*)src)[p];
        const float2 d = ((const float2*)dest)[p];
        const float2 a = ((const float2*)ea)[p];

        long long i0, i1;
        if (is64) {
            longlong2 bi = ((const longlong2*)batch_raw)[p];
            i0 = bi.x; i1 = bi.y;
        } else {
            int2 bi = ((const int2*)batch_raw)[p];
            i0 = bi.x; i1 = bi.y;
        }
        const float u0 = __ldg(&u[i0]);
        const float u1 = __ldg(&u[i1]);

        const u64 sp = pack2(s.x, s.y);
        const u64 dp = pack2(d.x, d.y);
        const u64 ap = pack2(a.x, a.y);
        const u64 up = pack2(u0, u1);

        // layer 1
        u64 h[10];
        #pragma unroll
        for (int k = 0; k < 10; k++) {
            u64 acc = b1p[k];
            acc = fma2(sp, w1p[k],      acc);
            acc = fma2(dp, w1p[10 + k], acc);
            acc = fma2(ap, w1p[20 + k], acc);
            acc = fma2(up, w1p[30 + k], acc);
            h[k] = relu2(acc);
        }

        // layer 2 into smem output tile.
        // Partial unroll: keeps only ~2 iterations of LDS.128 weight temps
        // live instead of all 95 (R4's 255-reg blowup).
        float* row0 = &otile[(2 * t)     * 19];
        float* row1 = &otile[(2 * t + 1) * 19];
        #pragma unroll 2
        for (int j = 0; j < 19; j++) {
            u64 acc = b2p[j];
            const ulonglong2* wr = (const ulonglong2*)&w2p[j * 10];  // 16B aligned
            #pragma unroll
            for (int kk = 0; kk < 5; kk++) {
                ulonglong2 w = wr[kk];
                acc = fma2(h[2 * kk],     w.x, acc);
                acc = fma2(h[2 * kk + 1], w.y, acc);
            }
            float lo, hi;
            unpack2(acc, lo, hi);
            row0[j] = lo;
            row1[j] = hi;
        }
        __syncthreads();

        // coalesced cooperative store: 512*19 floats = 2432 float4
        const float4* ot4 = (const float4*)otile;
        float4* o4 = (float4*)(out + base * 19);   // base*19 % 4 == 0
        #pragma unroll
        for (int i = 0; i < 2432 / TPB; i++)
            o4[i * TPB + t] = ot4[i * TPB + t];
        {   // remainder: 2432 = 9*256 + 128
            int i = (2432 / TPB) * TPB + t;
            if (i < 2432) o4[i] = ot4[i];
        }
    } else {
        // ================= tail path (scalar, bounds-checked) =================
        for (long long e = base + t; e < E; e += TPB) {
            float x0 = src[e], x1 = dest[e], x2 = ea[e];
            long long bi = is64 ? ((const long long*)batch_raw)[e]
                                : (long long)((const int*)batch_raw)[e];
            float x3 = u[bi];
            float h[10];
            #pragma unroll
            for (int k = 0; k < 10; k++) {
                float acc = b1[k];
                acc = fmaf(x0, W1[k],      acc);
                acc = fmaf(x1, W1[10 + k], acc);
                acc = fmaf(x2, W1[20 + k], acc);
                acc = fmaf(x3, W1[30 + k], acc);
                h[k] = fmaxf(acc, 0.0f);
            }
            #pragma unroll
            for (int j = 0; j < 19; j++) {
                float acc = b2[j];
                #pragma unroll
                for (int k = 0; k < 10; k++)
                    acc = fmaf(h[k], W2[k * 19 + j], acc);
                out[e * 19 + j] = acc;
            }
        }
    }
}

extern "C" void kernel_launch(void* const* d_in, const int* in_sizes, int n_in,
                              void* d_out, int out_size)
{
    const float* src   = (const float*)d_in[0];
    const float* dest  = (const float*)d_in[1];
    const float* ea    = (const float*)d_in[2];
    const float* u     = (const float*)d_in[3];
    const void*  batch = d_in[4];
    const float* W1    = (const float*)d_in[5];
    const float* b1    = (const float*)d_in[6];
    const float* W2    = (const float*)d_in[7];
    const float* b2    = (const float*)d_in[8];
    float* out = (float*)d_out;

    const long long E = in_sizes[0];
    const int blocks = (int)((E + EDGES_PER_BLOCK - 1) / EDGES_PER_BLOCK);

    detect_batch_dtype<<<1, 32>>>((const int*)batch);
    edge_model_kernel<<<blocks, TPB>>>(src, dest, ea, u, batch,
                                       W1, b1, W2, b2, out, E);
}